// round 1
// baseline (speedup 1.0000x reference)
#include <cuda_runtime.h>
#include <math.h>

#define N_AG   512
#define H_DIM  128
#define E_DIM  64
#define XDIM   320
#define GDIM   512
#define KPOOL  2048
#define NSPLIT 16

// ---------------- persistent device state ----------------
__device__ float g_obs[16 * 1024];                 // imputed positions [T][512][2]
__device__ float g_hs[N_AG * H_DIM];
__device__ float g_cs[N_AG * H_DIM];
__device__ float g_X[N_AG * XDIM];                 // [emb(64) | soc(128) | hs(128)]
__device__ float g_grid[N_AG * KPOOL];             // pooled grid, [i][cell*128+h]
__device__ float g_socpart[NSPLIT * N_AG * H_DIM]; // split-K partials
__device__ float g_gates[N_AG * GDIM];
__device__ float g_Wcat[2 * GDIM * XDIM];          // [enc|dec] concat of W_ih | W_hh
__device__ float g_bsum[2 * GDIM];                 // b_ih + b_hh
__device__ float g_curr[N_AG * 2];
__device__ float g_prev[N_AG * 2];

__device__ __forceinline__ float sigf(float x) { return 1.0f / (1.0f + expf(-x)); }

// ---------------- setup: impute + zero state + concat weights ----------------
__global__ void setup_kernel(const float* __restrict__ observed, int T,
                             const float* __restrict__ Wih_e, const float* __restrict__ bih_e,
                             const float* __restrict__ Whh_e, const float* __restrict__ bhh_e,
                             const float* __restrict__ Wih_d, const float* __restrict__ bih_d,
                             const float* __restrict__ Whh_d, const float* __restrict__ bhh_d)
{
    int gtid = blockIdx.x * blockDim.x + threadIdx.x;
    int nth  = gridDim.x * blockDim.x;

    // imputation: backfill leading gaps with first valid, forward-fill later, 0 if never valid
    for (int i = gtid; i < N_AG; i += nth) {
        int firstv = -1;
        for (int t = 0; t < T; t++) {
            float x = observed[t * 1024 + i * 2], y = observed[t * 1024 + i * 2 + 1];
            if (isfinite(x) && isfinite(y)) { firstv = t; break; }
        }
        int last = -1;
        for (int t = 0; t < T; t++) {
            float x = observed[t * 1024 + i * 2], y = observed[t * 1024 + i * 2 + 1];
            if (isfinite(x) && isfinite(y)) last = t;
            int take = (last >= 0) ? last : firstv;
            float ox = 0.0f, oy = 0.0f;
            if (firstv >= 0) {
                ox = observed[take * 1024 + i * 2];
                oy = observed[take * 1024 + i * 2 + 1];
            }
            g_obs[t * 1024 + i * 2]     = ox;
            g_obs[t * 1024 + i * 2 + 1] = oy;
        }
    }
    for (int idx = gtid; idx < N_AG * H_DIM; idx += nth) { g_hs[idx] = 0.0f; g_cs[idx] = 0.0f; }
    // concatenated weights: Wcat[g][0:192]=W_ih[g], Wcat[g][192:320]=W_hh[g]
    for (int idx = gtid; idx < GDIM * XDIM; idx += nth) {
        int g = idx / XDIM, k = idx - g * XDIM;
        g_Wcat[idx]               = (k < 192) ? Wih_e[g * 192 + k] : Whh_e[g * 128 + (k - 192)];
        g_Wcat[GDIM * XDIM + idx] = (k < 192) ? Wih_d[g * 192 + k] : Whh_d[g * 128 + (k - 192)];
    }
    for (int g = gtid; g < GDIM; g += nth) {
        g_bsum[g]        = bih_e[g] + bhh_e[g];
        g_bsum[GDIM + g] = bih_d[g] + bhh_d[g];
    }
}

// ---------------- pooling + emb + hs-copy ----------------
// one CTA per agent i, 128 threads (thread t = hidden lane t)
__global__ void pool_kernel(int pos_mode, int prev_mode,
                            const float* __restrict__ W_pos, const float* __restrict__ b_pos)
{
    __shared__ float s_grid[16 * 128];
    __shared__ int   s_list[512];
    __shared__ int   s_cnt;

    int i = blockIdx.x;
    int t = threadIdx.x;
    const float* posbuf  = (pos_mode  >= 0) ? (g_obs + pos_mode  * 1024) : g_curr;
    const float* prevbuf = (prev_mode >= 0) ? (g_obs + prev_mode * 1024) : g_prev;

    const float NEG_INF = -__int_as_float(0x7f800000);
    if (t == 0) s_cnt = 0;
#pragma unroll
    for (int c = 0; c < 16; c++) s_grid[c * 128 + t] = NEG_INF;

    float px = posbuf[i * 2], py = posbuf[i * 2 + 1];
    __syncthreads();

    // phase 1: build compact neighbor list (j, cell)
#pragma unroll
    for (int q = 0; q < 4; q++) {
        int j = t + q * 128;
        float jx = posbuf[j * 2], jy = posbuf[j * 2 + 1];
        float dx = jx - px, dy = jy - py;
        // NaN/Inf positions fail these compares -> excluded, matching reference finiteness mask
        if (j != i && fabsf(dx) <= 1.0f && fabsf(dy) <= 1.0f) {
            int gx = (int)floorf((dx + 1.0f) * 2.0f); gx = min(3, max(0, gx));
            int gy = (int)floorf((dy + 1.0f) * 2.0f); gy = min(3, max(0, gy));
            int cid  = gx * 4 + gy;
            int slot = atomicAdd(&s_cnt, 1);
            s_list[slot] = (j << 4) | cid;
        }
    }
    __syncthreads();
    int cnt = s_cnt;

    // phase 2: max-pool hidden of each neighbor into its cell (thread t owns lane t: race-free)
    int e = 0;
    for (; e + 4 <= cnt; e += 4) {
        int p0 = s_list[e], p1 = s_list[e + 1], p2 = s_list[e + 2], p3 = s_list[e + 3];
        float v0 = g_hs[(p0 >> 4) * 128 + t];
        float v1 = g_hs[(p1 >> 4) * 128 + t];
        float v2 = g_hs[(p2 >> 4) * 128 + t];
        float v3 = g_hs[(p3 >> 4) * 128 + t];
        int a0 = (p0 & 15) * 128 + t, a1 = (p1 & 15) * 128 + t;
        int a2 = (p2 & 15) * 128 + t, a3 = (p3 & 15) * 128 + t;
        s_grid[a0] = fmaxf(s_grid[a0], v0);
        s_grid[a1] = fmaxf(s_grid[a1], v1);
        s_grid[a2] = fmaxf(s_grid[a2], v2);
        s_grid[a3] = fmaxf(s_grid[a3], v3);
    }
    for (; e < cnt; e++) {
        int p = s_list[e];
        float v = g_hs[(p >> 4) * 128 + t];
        int a = (p & 15) * 128 + t;
        s_grid[a] = fmaxf(s_grid[a], v);
    }

    // write pooled grid (empty cell -> 0)
#pragma unroll
    for (int c = 0; c < 16; c++) {
        float v = s_grid[c * 128 + t];
        g_grid[i * KPOOL + c * 128 + t] = (v == NEG_INF) ? 0.0f : v;
    }

    // velocity embedding -> X[0:64]
    if (t < E_DIM) {
        float vx = px - prevbuf[i * 2];
        float vy = py - prevbuf[i * 2 + 1];
        float ev = b_pos[t] + vx * W_pos[t * 2] + vy * W_pos[t * 2 + 1];
        g_X[i * XDIM + t] = fmaxf(ev, 0.0f);
    }
    // hs snapshot -> X[192:320]
    g_X[i * XDIM + 192 + t] = g_hs[i * H_DIM + t];
}

// ---------------- GEMM1: socpart[ks] = grid[:, ks*128:(ks+1)*128] @ W_pool_chunk^T ----------------
// grid: (8 row-tiles of 64, 16 K-splits of 128); 256 threads; C-tile 64x128
__global__ void gemm1_kernel(const float* __restrict__ W_pool)
{
    __shared__ float As[16][65];
    __shared__ float Bs[16][129];
    int tid = threadIdx.x;
    int tx = tid & 15;      // col group: cols tx + j*16
    int ty = tid >> 4;      // row group: rows ty*4 + i
    int row0 = blockIdx.x * 64;
    int kb   = blockIdx.y * 128;

    float acc[4][8];
#pragma unroll
    for (int a = 0; a < 4; a++)
#pragma unroll
        for (int b = 0; b < 8; b++) acc[a][b] = 0.0f;

    for (int kk = 0; kk < 128; kk += 16) {
        {   // A: 64 rows x 16 k
            int m  = tid >> 2;
            int k4 = (tid & 3) * 4;
            float4 v = *(const float4*)&g_grid[(row0 + m) * KPOOL + kb + kk + k4];
            As[k4 + 0][m] = v.x; As[k4 + 1][m] = v.y; As[k4 + 2][m] = v.z; As[k4 + 3][m] = v.w;
        }
        {   // B: 128 n x 16 k (transposed into Bs[k][n])
            int n  = tid >> 1;
            int k4 = (tid & 1) * 8;
            const float* bp = &W_pool[n * KPOOL + kb + kk + k4];
            float4 v0 = *(const float4*)bp;
            float4 v1 = *(const float4*)(bp + 4);
            Bs[k4 + 0][n] = v0.x; Bs[k4 + 1][n] = v0.y; Bs[k4 + 2][n] = v0.z; Bs[k4 + 3][n] = v0.w;
            Bs[k4 + 4][n] = v1.x; Bs[k4 + 5][n] = v1.y; Bs[k4 + 6][n] = v1.z; Bs[k4 + 7][n] = v1.w;
        }
        __syncthreads();
#pragma unroll
        for (int k = 0; k < 16; k++) {
            float a[4], b[8];
#pragma unroll
            for (int ii = 0; ii < 4; ii++) a[ii] = As[k][ty * 4 + ii];
#pragma unroll
            for (int jj = 0; jj < 8; jj++) b[jj] = Bs[k][tx + jj * 16];
#pragma unroll
            for (int ii = 0; ii < 4; ii++)
#pragma unroll
                for (int jj = 0; jj < 8; jj++) acc[ii][jj] = fmaf(a[ii], b[jj], acc[ii][jj]);
        }
        __syncthreads();
    }

    float* outp = &g_socpart[blockIdx.y * (N_AG * H_DIM)];
#pragma unroll
    for (int ii = 0; ii < 4; ii++) {
        int row = row0 + ty * 4 + ii;
#pragma unroll
        for (int jj = 0; jj < 8; jj++) {
            outp[row * H_DIM + tx + jj * 16] = acc[ii][jj];
        }
    }
}

// ---------------- split-K reduce + bias + relu -> X[64:192] ----------------
__global__ void socreduce_kernel(const float* __restrict__ b_pool)
{
    int idx = blockIdx.x * blockDim.x + threadIdx.x;   // 0..65535
    float s = 0.0f;
#pragma unroll
    for (int p = 0; p < NSPLIT; p++) s += g_socpart[p * (N_AG * H_DIM) + idx];
    int h = idx & 127;
    int i = idx >> 7;
    g_X[i * XDIM + 64 + h] = fmaxf(s + b_pool[h], 0.0f);
}

// ---------------- GEMM2: gates = X @ Wcat^T + bsum ----------------
// grid: (16 row-tiles of 32, 8 col-tiles of 64); 256 threads; C-tile 32x64
__global__ void gemm2_kernel(int wsel)
{
    __shared__ float As[16][33];
    __shared__ float Bs[16][65];
    int tid = threadIdx.x;
    int tx = tid & 15;      // cols tx + j*16
    int ty = tid >> 4;      // rows ty*2 + i
    int row0 = blockIdx.x * 32;
    int col0 = blockIdx.y * 64;
    const float* Wcat = &g_Wcat[wsel * GDIM * XDIM];

    float acc[2][4];
#pragma unroll
    for (int a = 0; a < 2; a++)
#pragma unroll
        for (int b = 0; b < 4; b++) acc[a][b] = 0.0f;

    for (int kk = 0; kk < XDIM; kk += 16) {
        {   // A: 32 rows x 16 k
            int m  = tid >> 3;
            int k2 = (tid & 7) * 2;
            float2 v = *(const float2*)&g_X[(row0 + m) * XDIM + kk + k2];
            As[k2 + 0][m] = v.x; As[k2 + 1][m] = v.y;
        }
        {   // B: 64 n x 16 k
            int n  = tid >> 2;
            int k4 = (tid & 3) * 4;
            float4 v = *(const float4*)&Wcat[(col0 + n) * XDIM + kk + k4];
            Bs[k4 + 0][n] = v.x; Bs[k4 + 1][n] = v.y; Bs[k4 + 2][n] = v.z; Bs[k4 + 3][n] = v.w;
        }
        __syncthreads();
#pragma unroll
        for (int k = 0; k < 16; k++) {
            float a[2], b[4];
#pragma unroll
            for (int ii = 0; ii < 2; ii++) a[ii] = As[k][ty * 2 + ii];
#pragma unroll
            for (int jj = 0; jj < 4; jj++) b[jj] = Bs[k][tx + jj * 16];
#pragma unroll
            for (int ii = 0; ii < 2; ii++)
#pragma unroll
                for (int jj = 0; jj < 4; jj++) acc[ii][jj] = fmaf(a[ii], b[jj], acc[ii][jj]);
        }
        __syncthreads();
    }

#pragma unroll
    for (int ii = 0; ii < 2; ii++) {
        int row = row0 + ty * 2 + ii;
#pragma unroll
        for (int jj = 0; jj < 4; jj++) {
            int col = col0 + tx + jj * 16;
            g_gates[row * GDIM + col] = acc[ii][jj] + g_bsum[wsel * GDIM + col];
        }
    }
}

// ---------------- LSTM pointwise (+ decoder output) ----------------
// one CTA per agent, 128 threads
__global__ void lstm_kernel(int is_dec, int step, int pos_mode,
                            const float* __restrict__ W_out, const float* __restrict__ b_out,
                            float* __restrict__ out)
{
    int i = blockIdx.x;
    int h = threadIdx.x;

    float gi = g_gates[i * GDIM + h];
    float gf = g_gates[i * GDIM + 128 + h];
    float gg = g_gates[i * GDIM + 256 + h];
    float go = g_gates[i * GDIM + 384 + h];
    float c  = g_cs[i * H_DIM + h];
    float c2 = sigf(gf) * c + sigf(gi) * tanhf(gg);
    float h2 = sigf(go) * tanhf(c2);
    g_cs[i * H_DIM + h] = c2;
    g_hs[i * H_DIM + h] = h2;

    if (is_dec) {
        __shared__ float s0[128], s1[128];
        s0[h] = h2 * W_out[h];
        s1[h] = h2 * W_out[128 + h];
        __syncthreads();
#pragma unroll
        for (int off = 64; off > 0; off >>= 1) {
            if (h < off) { s0[h] += s0[h + off]; s1[h] += s1[h + off]; }
            __syncthreads();
        }
        if (h == 0) {
            const float* posbuf = (pos_mode >= 0) ? (g_obs + pos_mode * 1024) : g_curr;
            float px = posbuf[i * 2], py = posbuf[i * 2 + 1];
            float nx = px + s0[0] + b_out[0];
            float ny = py + s1[0] + b_out[1];
            out[step * 1024 + i * 2]     = nx;
            out[step * 1024 + i * 2 + 1] = ny;
            g_prev[i * 2] = px; g_prev[i * 2 + 1] = py;
            g_curr[i * 2] = nx; g_curr[i * 2 + 1] = ny;
        }
    }
}

// ---------------- launch ----------------
extern "C" void kernel_launch(void* const* d_in, const int* in_sizes, int n_in,
                              void* d_out, int out_size)
{
    const float* observed = (const float*)d_in[0];
    const float* W_pos    = (const float*)d_in[1];
    const float* b_pos    = (const float*)d_in[2];
    const float* W_pool   = (const float*)d_in[3];
    const float* b_pool   = (const float*)d_in[4];
    const float* Wih_e    = (const float*)d_in[5];
    const float* bih_e    = (const float*)d_in[6];
    const float* Whh_e    = (const float*)d_in[7];
    const float* bhh_e    = (const float*)d_in[8];
    const float* Wih_d    = (const float*)d_in[9];
    const float* bih_d    = (const float*)d_in[10];
    const float* Whh_d    = (const float*)d_in[11];
    const float* bhh_d    = (const float*)d_in[12];
    const float* W_out    = (const float*)d_in[13];
    const float* b_out    = (const float*)d_in[14];
    float* out = (float*)d_out;

    int T = in_sizes[0] / (N_AG * 2);
    if (T > 16) T = 16;
    int npred = out_size / (N_AG * 2);

    setup_kernel<<<64, 256>>>(observed, T, Wih_e, bih_e, Whh_e, bhh_e,
                              Wih_d, bih_d, Whh_d, bhh_d);

    // encoder: step s uses pos=obs[s+1], prev=obs[s]
    for (int s = 0; s < T - 1; s++) {
        pool_kernel<<<512, 128>>>(s + 1, s, W_pos, b_pos);
        gemm1_kernel<<<dim3(8, 16), 256>>>(W_pool);
        socreduce_kernel<<<256, 256>>>(b_pool);
        gemm2_kernel<<<dim3(16, 8), 256>>>(0);
        lstm_kernel<<<512, 128>>>(0, 0, 0, W_out, b_out, out);
    }

    // decoder: step 0 uses pos=prev=obs[T-1]; later steps use curr/prev carries
    for (int s = 0; s < npred; s++) {
        int pm = (s == 0) ? (T - 1) : -1;   // pos: obs[T-1] or g_curr
        int vm = (s == 0) ? (T - 1) : -2;   // prev: obs[T-1] or g_prev
        pool_kernel<<<512, 128>>>(pm, vm, W_pos, b_pos);
        gemm1_kernel<<<dim3(8, 16), 256>>>(W_pool);
        socreduce_kernel<<<256, 256>>>(b_pool);
        gemm2_kernel<<<dim3(16, 8), 256>>>(1);
        lstm_kernel<<<512, 128>>>(1, s, pm, W_out, b_out, out);
    }
}